// round 13
// baseline (speedup 1.0000x reference)
#include <cuda_runtime.h>
#include <cstdint>

#define BB 20
#define LL 20
#define VV 100000
#define NP (BB * LL * LL)   // 8000 gathered elements
#define PAD_LO 288          // floats of front padding (covers -18c-20 offsets)
#define PAD_HI 192          // floats of back padding

// Padded scratch: device globals are zero-initialized, so the pad reads used
// by inactive (predicated-off) lanes are in-bounds and harmless.
__device__ float g_Ppad[PAD_LO + NP + PAD_HI];

// ---------------------------------------------------------------------------
// Kernel A: distributed gather across 125 blocks (spreads the 8000 scattered
// 128B-line accesses over many SMs' L1tex queues). Signals PDL dependents.
// ---------------------------------------------------------------------------
__global__ void __launch_bounds__(64) gather_kernel(
    const float* __restrict__ topic_prob,
    const int*   __restrict__ hard_label)
{
    const int i = blockIdx.x * 64 + threadIdx.x;   // 125*64 == 8000 exactly
    const int b = i / (LL * LL);
    const int j = (i / LL) % LL;
    const int k = i % LL;
    const int lab = __ldg(&hard_label[b * LL + k]);
    const int idx = lab < 0 ? 0 : (lab > (VV - 1) ? (VV - 1) : lab);
    g_Ppad[PAD_LO + i] = __ldg(&topic_prob[(size_t)(b * LL + j) * VV + idx]);
    asm volatile("griddepcontrol.launch_dependents;");
}

// ---------------------------------------------------------------------------
// Kernel B (PDL dependent): launches while A runs; does all P-independent
// work before griddepcontrol.wait, then runs the anti-diagonal wavefront DP
// reading P DIRECTLY from L2-hot g_Ppad (coalesced: one 128B line per
// 16-lane segment per step; addresses affine in the unrolled step index, so
// ptxas batches the scoreboarded loads and the L2 latency hides under the
// shfl chain). No smem staging at all.
// 10 warps; warp w = batches {2w, 2w+1} in 16-lane segments; lane c owns DP
// columns 2c+1, 2c+2; one segmented shfl per step (diag = prior left).
// ---------------------------------------------------------------------------
__global__ void __launch_bounds__(320) dp_kernel(
    const int* __restrict__ hard_label,
    float*     __restrict__ out)
{
    __shared__ float s_loss[BB];

    const int tid  = threadIdx.x;
    const int warp = tid >> 5;
    const int lane = tid & 31;
    const int sub  = lane & 15;
    const int half = lane >> 4;

    // ---- pre-wait phase: everything that doesn't touch g_Ppad ----
    const int b0 = 2 * warp, b1 = 2 * warp + 1;
    const int l0 = (lane < LL) ? __ldg(&hard_label[b0 * LL + lane]) : -1;
    const unsigned bal0 = __ballot_sync(0xFFFFFFFFu, (lane < LL) && (l0 >= 0));
    const int l1 = (lane < LL) ? __ldg(&hard_label[b1 * LL + lane]) : -1;
    const unsigned bal1 = __ballot_sync(0xFFFFFFFFu, (lane < LL) && (l1 >= 0));

    const unsigned bal = half ? bal1 : bal0;
    const int len = __popc(bal & 0xFFFFFu);
    const int b   = half ? b1 : b0;
    const int c   = sub;

    // P base pointer for this lane (pad keeps all unrolled offsets in-bounds)
    const float* __restrict__ pbase =
        g_Ppad + PAD_LO + b * (LL * LL) - 18 * c - LL;

    const bool capA  = (2 * c + 1 == len);
    const bool capB  = (2 * c + 2 == len);
    const bool valid = (c < 10);

    // ---- wait for kernel A's g_Ppad writes to be visible ----
    asm volatile("griddepcontrol.wait;" ::: "memory");

    float prevA = 0.0f, prevB = 0.0f, dleft = 0.0f, result = 0.0f;

    if (bal0 == 0xFFFFFu && bal1 == 0xFFFFFu) {
        // fast path: all masks set (always for this data)
        #pragma unroll
        for (int t = 1; t <= LL + 9; ++t) {
            const float2 p2 = __ldg((const float2*)(pbase + t * LL));

            float left = __shfl_up_sync(0xFFFFFFFFu, prevB, 1, 16);
            if (sub == 0) left = 0.0f;
            const float diag = dleft;
            dleft = left;

            const int  j   = t - c;
            const bool act = valid && (j >= 1) && (j <= LL);

            const float Ma = fmaxf(left, prevA);
            const float vA = fmaf(p2.x, diag + 1.0f - Ma, Ma);
            const float Mb = fmaxf(vA, prevB);
            const float vB = fmaf(p2.y, prevA + 1.0f - Mb, Mb);

            if (act) {
                if (j == len) {
                    if (capA) result = vA;
                    if (capB) result = vB;
                }
                prevA = vA;
                prevB = vB;
            }
        }
    } else {
        // general path: per-cell mask zeroing
        const unsigned bitA = (bal >> (2 * c)) & 1u;
        const unsigned bitB = (bal >> (2 * c + 1)) & 1u;
        #pragma unroll
        for (int t = 1; t <= LL + 9; ++t) {
            const float2 p2 = __ldg((const float2*)(pbase + t * LL));

            float left = __shfl_up_sync(0xFFFFFFFFu, prevB, 1, 16);
            if (sub == 0) left = 0.0f;
            const float diag = dleft;
            dleft = left;

            const int  j   = t - c;
            const bool act = valid && (j >= 1) && (j <= LL);
            const int  js  = (j < 1) ? 1 : (j > LL ? LL : j);
            const unsigned mj = (bal >> (js - 1)) & 1u;

            const float Ma = fmaxf(left, prevA);
            float vA = fmaf(p2.x, diag + 1.0f - Ma, Ma);
            vA = (mj & bitA) ? vA : 0.0f;
            const float Mb = fmaxf(vA, prevB);
            float vB = fmaf(p2.y, prevA + 1.0f - Mb, Mb);
            vB = (mj & bitB) ? vB : 0.0f;

            if (act) {
                if (j == len) {
                    if (capA) result = vA;
                    if (capB) result = vB;
                }
                prevA = vA;
                prevB = vB;
            }
        }
    }

    if (len > 0) {
        if ((capA || capB) && valid)
            s_loss[b] = -logf(result / (float)len);
    } else if (sub == 0) {
        s_loss[b] = -logf(0.0f / 0.0f);   // 0/0 -> nan, matches reference
    }
    __syncthreads();

    if (warp == 0) {
        float v = (lane < BB) ? s_loss[lane] : 0.0f;
        #pragma unroll
        for (int off = 16; off > 0; off >>= 1)
            v += __shfl_down_sync(0xFFFFFFFFu, v, off);
        if (lane == 0) out[0] = v * (1.0f / (float)BB);
    }
}

extern "C" void kernel_launch(void* const* d_in, const int* in_sizes, int n_in,
                              void* d_out, int out_size) {
    const float* topic_prob = (const float*)d_in[0];
    const int*   hard_label = (const int*)d_in[1];
    float*       out        = (float*)d_out;

    gather_kernel<<<NP / 64, 64>>>(topic_prob, hard_label);

    cudaLaunchConfig_t cfg = {};
    cfg.gridDim  = dim3(1, 1, 1);
    cfg.blockDim = dim3(320, 1, 1);
    cfg.dynamicSmemBytes = 0;
    cfg.stream = 0;
    cudaLaunchAttribute attr;
    attr.id = cudaLaunchAttributeProgrammaticStreamSerialization;
    attr.val.programmaticStreamSerializationAllowed = 1;
    cfg.attrs = &attr;
    cfg.numAttrs = 1;
    cudaLaunchKernelEx(&cfg, dp_kernel, hard_label, out);
}

// round 14
// speedup vs baseline: 1.5314x; 1.5314x over previous
#include <cuda_runtime.h>

#define BB 20
#define LL 20
#define VV 100000
#define NP (BB * LL * LL)   // 8000 gathered elements

__device__ float g_P[NP];   // gathered P scratch (32 KB)

// ---------------------------------------------------------------------------
// Kernel A: distributed gather across 125 blocks (spreads the 8000 scattered
// 128B-line accesses over many SMs' L1tex queues). Signals PDL dependents.
// ---------------------------------------------------------------------------
__global__ void __launch_bounds__(64) gather_kernel(
    const float* __restrict__ topic_prob,
    const int*   __restrict__ hard_label)
{
    const int i = blockIdx.x * 64 + threadIdx.x;   // 125*64 == 8000 exactly
    const int b = i / (LL * LL);
    const int j = (i / LL) % LL;
    const int k = i % LL;
    const int lab = __ldg(&hard_label[b * LL + k]);
    const int idx = lab < 0 ? 0 : (lab > (VV - 1) ? (VV - 1) : lab);
    g_P[i] = __ldg(&topic_prob[(size_t)(b * LL + j) * VV + idx]);
    asm volatile("griddepcontrol.launch_dependents;");
}

// ---------------------------------------------------------------------------
// Kernel B (PDL dependent): launches while A runs; does all P-independent
// work (labels, ballots, constants) before griddepcontrol.wait, then stages
// its warp's two batches of P into smem (single up-front L2 trip, full MLP)
// and runs the anti-diagonal wavefront DP. 10 warps; warp w = batches
// {2w, 2w+1} in 16-lane segments; lane c owns DP columns 2c+1, 2c+2; one
// segmented shfl per step (diag = previous step's left).
// ---------------------------------------------------------------------------
#define PAD_LO 288
#define PAD_HI 192

__global__ void __launch_bounds__(320) dp_kernel(
    const int* __restrict__ hard_label,
    float*     __restrict__ out)
{
    __shared__ float4 s_buf4[(PAD_LO + NP + PAD_HI) / 4];
    __shared__ float  s_loss[BB];
    float* s_P = ((float*)s_buf4) + PAD_LO;

    const int tid  = threadIdx.x;
    const int warp = tid >> 5;
    const int lane = tid & 31;
    const int sub  = lane & 15;
    const int half = lane >> 4;

    // ---- pre-wait phase: everything that doesn't touch g_P ----
    const int b0 = 2 * warp, b1 = 2 * warp + 1;
    const int l0 = (lane < LL) ? __ldg(&hard_label[b0 * LL + lane]) : -1;
    const unsigned bal0 = __ballot_sync(0xFFFFFFFFu, (lane < LL) && (l0 >= 0));
    const int l1 = (lane < LL) ? __ldg(&hard_label[b1 * LL + lane]) : -1;
    const unsigned bal1 = __ballot_sync(0xFFFFFFFFu, (lane < LL) && (l1 >= 0));

    const unsigned bal = half ? bal1 : bal0;
    const int len = __popc(bal & 0xFFFFFu);
    const int b   = half ? b1 : b0;
    const int c   = sub;

    const int  base  = b * (LL * LL) - 18 * c - LL;   // s_P index at t=0
    const bool capA  = (2 * c + 1 == len);
    const bool capB  = (2 * c + 2 == len);
    const bool valid = (c < 10);

    // ---- wait for kernel A's g_P writes to be visible ----
    asm volatile("griddepcontrol.wait;" ::: "memory");

    // warp-local staging: this warp's two batches (200 float4), L2-hot
    {
        const float4* __restrict__ src = ((const float4*)g_P) + b0 * 100;
        float4* dst = (float4*)(s_P + b0 * (LL * LL));
        #pragma unroll
        for (int i = lane; i < 200; i += 32)
            dst[i] = src[i];
    }
    __syncwarp();

    float prevA = 0.0f, prevB = 0.0f, dleft = 0.0f, result = 0.0f;

    if (bal0 == 0xFFFFFu && bal1 == 0xFFFFFu) {
        // fast path: all masks set (always for this data)
        #pragma unroll
        for (int t = 1; t <= LL + 9; ++t) {
            float left = __shfl_up_sync(0xFFFFFFFFu, prevB, 1, 16);
            if (sub == 0) left = 0.0f;
            const float diag = dleft;
            dleft = left;

            const int  j   = t - c;
            const bool act = valid && (j >= 1) && (j <= LL);

            const float2 p2 = *(const float2*)(s_P + base + t * LL);

            const float Ma = fmaxf(left, prevA);
            const float vA = fmaf(p2.x, diag + 1.0f - Ma, Ma);
            const float Mb = fmaxf(vA, prevB);
            const float vB = fmaf(p2.y, prevA + 1.0f - Mb, Mb);

            if (act) {
                if (j == len) {
                    if (capA) result = vA;
                    if (capB) result = vB;
                }
                prevA = vA;
                prevB = vB;
            }
        }
    } else {
        // general path: per-cell mask zeroing
        const unsigned bitA = (bal >> (2 * c)) & 1u;
        const unsigned bitB = (bal >> (2 * c + 1)) & 1u;
        #pragma unroll
        for (int t = 1; t <= LL + 9; ++t) {
            float left = __shfl_up_sync(0xFFFFFFFFu, prevB, 1, 16);
            if (sub == 0) left = 0.0f;
            const float diag = dleft;
            dleft = left;

            const int  j   = t - c;
            const bool act = valid && (j >= 1) && (j <= LL);
            const int  js  = (j < 1) ? 1 : (j > LL ? LL : j);
            const unsigned mj = (bal >> (js - 1)) & 1u;

            const float2 p2 = *(const float2*)(s_P + base + t * LL);

            const float Ma = fmaxf(left, prevA);
            float vA = fmaf(p2.x, diag + 1.0f - Ma, Ma);
            vA = (mj & bitA) ? vA : 0.0f;
            const float Mb = fmaxf(vA, prevB);
            float vB = fmaf(p2.y, prevA + 1.0f - Mb, Mb);
            vB = (mj & bitB) ? vB : 0.0f;

            if (act) {
                if (j == len) {
                    if (capA) result = vA;
                    if (capB) result = vB;
                }
                prevA = vA;
                prevB = vB;
            }
        }
    }

    if (len > 0) {
        if ((capA || capB) && valid)
            s_loss[b] = -logf(result / (float)len);
    } else if (sub == 0) {
        s_loss[b] = -logf(0.0f / 0.0f);   // 0/0 -> nan, matches reference
    }
    __syncthreads();

    if (warp == 0) {
        float v = (lane < BB) ? s_loss[lane] : 0.0f;
        #pragma unroll
        for (int off = 16; off > 0; off >>= 1)
            v += __shfl_down_sync(0xFFFFFFFFu, v, off);
        if (lane == 0) out[0] = v * (1.0f / (float)BB);
    }
}

extern "C" void kernel_launch(void* const* d_in, const int* in_sizes, int n_in,
                              void* d_out, int out_size) {
    const float* topic_prob = (const float*)d_in[0];
    const int*   hard_label = (const int*)d_in[1];
    float*       out        = (float*)d_out;

    gather_kernel<<<NP / 64, 64>>>(topic_prob, hard_label);

    // Dependent launch: B starts while A runs; B's griddepcontrol.wait
    // orders its g_P reads after A's completion.
    cudaLaunchConfig_t cfg = {};
    cfg.gridDim  = dim3(1, 1, 1);
    cfg.blockDim = dim3(320, 1, 1);
    cfg.dynamicSmemBytes = 0;
    cfg.stream = 0;
    cudaLaunchAttribute attr;
    attr.id = cudaLaunchAttributeProgrammaticStreamSerialization;
    attr.val.programmaticStreamSerializationAllowed = 1;
    cfg.attrs = &attr;
    cfg.numAttrs = 1;
    cudaLaunchKernelEx(&cfg, dp_kernel, hard_label, out);
}